// round 11
// baseline (speedup 1.0000x reference)
#include <cuda_runtime.h>
#include <cuda_fp16.h>
#include <cstdint>

// ============================================================================
// GGRUCell on GB300 — HMMA fp16 single-term GEMMs.
// R11: smem carries A only (cp.async 4 stages). B fragments come straight
// from L2 via ldg.128, REGISTER DOUBLE-BUFFERED: chunk c+1's B is prefetched
// right after chunk c's barrier, ~600 cyc before first use. This empties the
// L1/shared crossbar (R10's binder: STS+LDSM+LDS ≈ 370cyc/chunk vs MMA 256).
//
//   R   = sigmoid(prev @ Wr + inp[:,2H:]) * inp[:,:H]
//   out = mask * (tanh(R @ U + inp[:,:H]) + 1) + prev   (update gate cancels)
// ============================================================================

#define HDIM   1024
#define BATCH  16384

static constexpr int M_TILE = 128;
static constexpr int N_TILE = 64;
static constexpr int KT     = 32;            // K-chunk
static constexpr int NC     = HDIM / 32;     // 32 k32-granules
static constexpr int SA     = 40;            // padded smem row stride (fp16)
static constexpr int STAGES = 4;

static constexpr int A_BYTES     = 128 * SA * 2;          // 10240
static constexpr int STG_BYTES   = A_BYTES;
static constexpr int SMEM_BYTES  = STAGES * STG_BYTES;    // 40960

// --------------------------------------------------------------------------
__device__ __forceinline__ uint32_t smem_to_u32(const void* p) {
    uint32_t a;
    asm("{ .reg .u64 t; cvta.to.shared.u64 t, %1; cvt.u32.u64 %0, t; }" : "=r"(a) : "l"(p));
    return a;
}
#define CP_ASYNC16(s, g) \
    asm volatile("cp.async.cg.shared.global [%0], [%1], 16;" :: "r"(s), "l"(g) : "memory")
#define CP_COMMIT() asm volatile("cp.async.commit_group;" ::: "memory")
#define CP_WAIT2()  asm volatile("cp.async.wait_group 2;" ::: "memory")
#define CP_WAIT0()  asm volatile("cp.async.wait_group 0;" ::: "memory")

#define LDSM_X4(r0, r1, r2, r3, addr) \
    asm volatile("ldmatrix.sync.aligned.m8n8.x4.shared.b16 {%0,%1,%2,%3}, [%4];" \
                 : "=r"(r0), "=r"(r1), "=r"(r2), "=r"(r3) : "r"(addr))

#define MMA_F16_2(d, a, b0, b1) \
    asm volatile("mma.sync.aligned.m16n8k16.row.col.f32.f16.f16.f32 " \
                 "{%0,%1,%2,%3}, {%4,%5,%6,%7}, {%8,%9}, {%0,%1,%2,%3};" \
                 : "+f"((d)[0]), "+f"((d)[1]), "+f"((d)[2]), "+f"((d)[3]) \
                 : "r"((a)[0]), "r"((a)[1]), "r"((a)[2]), "r"((a)[3]), \
                   "r"(b0), "r"(b1))

// --------------------------------------------------------------------------
// Scratch (no cudaMalloc allowed)
// --------------------------------------------------------------------------
// B fragment-linear planes: index ((n8*NC + k32)*32 + lane) -> uint4 holding
// {b0,b1} for first k16 and {b0,b1} for second k16 of the k32 granule,
// per the m16n8k16 .col B layout (thread t: n=t/4, k=2*(t%4)+{0,1},+8,..).
__device__ uint4 g_W1f[(HDIM / 8) * NC * 32];
__device__ uint4 g_W2f[(HDIM / 8) * NC * 32];
__device__ __half g_Ph[(size_t)BATCH * HDIM];   // prev, fp16
__device__ __half g_Rh[(size_t)BATCH * HDIM];   // R = reset*state, fp16

__device__ __forceinline__ uint32_t pack_h2(__half a, __half b) {
    __half2 t; t.x = a; t.y = b;
    return *reinterpret_cast<uint32_t*>(&t);
}

// --------------------------------------------------------------------------
__global__ void wtrans_frag(const float* __restrict__ W, int ld, int off, int which) {
    const int t    = blockIdx.x * 256 + threadIdx.x;
    const int lane = t & 31;
    const int k32  = (t >> 5) & (NC - 1);
    const int n8   = t >> 10;
    const int n    = n8 * 8 + (lane >> 2);
    const int kb   = k32 * 32 + 2 * (lane & 3);
    uint32_t h[4];
#pragma unroll
    for (int w = 0; w < 4; w++) {
        const int k = kb + 8 * w;
        const float v0 = W[(size_t)k * ld + off + n];
        const float v1 = W[(size_t)(k + 1) * ld + off + n];
        h[w] = pack_h2(__float2half(v0), __float2half(v1));
    }
    uint4* F = which ? g_W2f : g_W1f;
    F[t] = make_uint4(h[0], h[1], h[2], h[3]);
}

// --------------------------------------------------------------------------
__global__ void psplit_kernel(const float* __restrict__ prev) {
    size_t i = ((size_t)blockIdx.x * 256 + threadIdx.x) * 4;
    float4 v = *reinterpret_cast<const float4*>(&prev[i]);
    uint32_t p01 = pack_h2(__float2half(v.x), __float2half(v.y));
    uint32_t p23 = pack_h2(__float2half(v.z), __float2half(v.w));
    *reinterpret_cast<uint2*>(&g_Ph[i]) = make_uint2(p01, p23);
}

// --------------------------------------------------------------------------
// GEMM: CTA 128x64, 8 warps (4M x 2N), warp tile 32x32, K-chunk 32,
// A: 4-stage cp.async + LDSM. B: ldg.128 from L2, register double-buffer.
// 3 CTAs/SM.
// --------------------------------------------------------------------------
template <bool FIRST>
__global__ void __launch_bounds__(256, 3)
gemm_kernel(const float* __restrict__ inp, const float* __restrict__ prev,
            const float* __restrict__ mask, float* __restrict__ out) {
    extern __shared__ char smem_raw[];
    const uint32_t sb = smem_to_u32(smem_raw);

    const int tid   = threadIdx.x;
    const int wid   = tid >> 5;
    const int lane  = tid & 31;
    const int warpM = wid >> 1;       // 4 warps over M (32 rows each)
    const int warpN = wid & 1;        // 2 warps over N (32 cols each)
    const int m0 = blockIdx.x * M_TILE;
    const int n0 = blockIdx.y * N_TILE;

    const __half* AHg = FIRST ? g_Ph : g_Rh;
    const uint4* __restrict__ BF = FIRST ? g_W1f : g_W2f;
    // this warp's 4 n8-tiles start here; consecutive chunks are +32 uint4
    const uint4* __restrict__ Bbase =
        BF + ((size_t)((n0 >> 3) + warpN * 4) * NC) * 32 + lane;

    auto issue_chunk = [&](int kc, int stage) {
        const uint32_t s0 = sb + stage * STG_BYTES;
#pragma unroll
        for (int i = 0; i < 2; i++) {
            const int g   = tid + i * 256;
            const int row = g >> 2;
            const int ce  = (g & 3) * 8;
            const size_t gA = (size_t)(m0 + row) * HDIM + kc * KT + ce;
            const uint32_t so = (uint32_t)(row * SA + ce) * 2;
            CP_ASYNC16(s0 + so, AHg + gA);
        }
    };

    float acc[2][4][4];
#pragma unroll
    for (int i = 0; i < 2; i++)
#pragma unroll
        for (int j = 0; j < 4; j++)
#pragma unroll
            for (int k = 0; k < 4; k++) acc[i][j][k] = 0.f;

    issue_chunk(0, 0); CP_COMMIT();
    issue_chunk(1, 1); CP_COMMIT();
    issue_chunk(2, 2); CP_COMMIT();

    // B for chunk 0 (only exposed L2 latency in the kernel)
    uint4 Bc[4];
#pragma unroll
    for (int ni = 0; ni < 4; ni++) Bc[ni] = __ldg(Bbase + (size_t)ni * NC * 32);

    for (int c = 0; c < NC; c++) {
        if (c == NC - 1) { CP_WAIT0(); } else { CP_WAIT2(); }
        __syncthreads();
        if (c + 3 < NC) {
            issue_chunk(c + 3, (c + 3) & 3);
            CP_COMMIT();
        }

        // prefetch next chunk's B into the shadow buffer (used next iter)
        uint4 Bn[4];
        if (c + 1 < NC) {
#pragma unroll
            for (int ni = 0; ni < 4; ni++)
                Bn[ni] = __ldg(Bbase + (size_t)(ni * NC + c + 1) * 32);
        }

        const uint32_t s0 = sb + (c & 3) * STG_BYTES;

#pragma unroll
        for (int kb2 = 0; kb2 < 2; kb2++) {
            const int kcol = kb2 * 16 + ((lane >> 4) << 3);
            uint32_t a0[4], a1[4];
            {
                const int r0 = warpM * 32 + (lane & 15);
                const int r1 = warpM * 32 + 16 + (lane & 15);
                const uint32_t o0 = (uint32_t)(r0 * SA + kcol) * 2;
                const uint32_t o1 = (uint32_t)(r1 * SA + kcol) * 2;
                LDSM_X4(a0[0], a0[1], a0[2], a0[3], s0 + o0);
                LDSM_X4(a1[0], a1[1], a1[2], a1[3], s0 + o1);
            }
#pragma unroll
            for (int ni = 0; ni < 4; ni++) {
                const uint32_t b0 = kb2 ? Bc[ni].z : Bc[ni].x;
                const uint32_t b1 = kb2 ? Bc[ni].w : Bc[ni].y;
                MMA_F16_2(acc[0][ni], a0, b0, b1);
                MMA_F16_2(acc[1][ni], a1, b0, b1);
            }
        }
#pragma unroll
        for (int ni = 0; ni < 4; ni++) Bc[ni] = Bn[ni];
    }

    // ---- epilogue ----
#pragma unroll
    for (int mi = 0; mi < 2; mi++) {
#pragma unroll
        for (int h = 0; h < 2; h++) {
            const int b = m0 + warpM * 32 + mi * 16 + h * 8 + (lane >> 2);
            float mval = 0.f;
            if (!FIRST) mval = __ldg(&mask[b]);
#pragma unroll
            for (int ni = 0; ni < 4; ni++) {
                const int n = n0 + warpN * 32 + ni * 8 + (lane & 3) * 2;
                const float v0 = acc[mi][ni][2 * h];
                const float v1 = acc[mi][ni][2 * h + 1];
                const float2 si = *reinterpret_cast<const float2*>(
                    &inp[(size_t)b * (3 * HDIM) + n]);
                if (FIRST) {
                    const float2 gi = *reinterpret_cast<const float2*>(
                        &inp[(size_t)b * (3 * HDIM) + 2 * HDIM + n]);
                    const float r0 = si.x / (1.f + __expf(-(v0 + gi.x)));
                    const float r1 = si.y / (1.f + __expf(-(v1 + gi.y)));
                    *reinterpret_cast<uint32_t*>(&g_Rh[(size_t)b * HDIM + n]) =
                        pack_h2(__float2half(r0), __float2half(r1));
                } else {
                    const float2 pv = *reinterpret_cast<const float2*>(
                        &prev[(size_t)b * HDIM + n]);
                    float2 o;
                    o.x = mval * (tanhf(v0 + si.x) + 1.f) + pv.x;
                    o.y = mval * (tanhf(v1 + si.y) + 1.f) + pv.y;
                    *reinterpret_cast<float2*>(&out[(size_t)b * HDIM + n]) = o;
                }
            }
        }
    }
}

// --------------------------------------------------------------------------
extern "C" void kernel_launch(void* const* d_in, const int* in_sizes, int n_in,
                              void* d_out, int out_size) {
    const float* inp  = (const float*)d_in[0];   // (B, 3H)
    const float* prev = (const float*)d_in[1];   // (B, H)
    const float* mask = (const float*)d_in[2];   // (B,)
    const float* Wur  = (const float*)d_in[3];   // (H, 2H)
    const float* U    = (const float*)d_in[4];   // (H, H)
    float* out = (float*)d_out;

    cudaFuncSetAttribute(gemm_kernel<true>,
                         cudaFuncAttributeMaxDynamicSharedMemorySize, SMEM_BYTES);
    cudaFuncSetAttribute(gemm_kernel<false>,
                         cudaFuncAttributeMaxDynamicSharedMemorySize, SMEM_BYTES);

    const int frag_slots = (HDIM / 8) * NC * 32;           // 131072
    wtrans_frag<<<frag_slots / 256, 256>>>(Wur, 2 * HDIM, HDIM, 0);  // Wr
    wtrans_frag<<<frag_slots / 256, 256>>>(U, HDIM, 0, 1);
    psplit_kernel<<<(BATCH * HDIM) / (256 * 4), 256>>>(prev);

    dim3 grid(BATCH / M_TILE, HDIM / N_TILE);
    gemm_kernel<true><<<grid, 256, SMEM_BYTES>>>(inp, prev, mask, out);
    gemm_kernel<false><<<grid, 256, SMEM_BYTES>>>(inp, prev, mask, out);
}

// round 12
// speedup vs baseline: 1.1033x; 1.1033x over previous
#include <cuda_runtime.h>
#include <cuda_fp16.h>
#include <cstdint>

// ============================================================================
// GGRUCell on GB300 — HMMA fp16 single-term GEMMs.
// R12 = R9 base (KT=64, 3-stage cp.async, CTA 128x128, 16 warps) +
//   (1) L2 prefetch of epilogue fp32/fp16 operands during the mainloop
//       (epilogue was a cold-DRAM serial tail ~600cyc/load),
//   (2) GEMM2 epilogue reads prev as fp16 from g_Ph (-32MB DRAM).
//
//   R   = sigmoid(prev @ Wr + inp[:,2H:]) * inp[:,:H]
//   out = mask * (tanh(R @ U + inp[:,:H]) + 1) + prev   (update gate cancels)
// ============================================================================

#define HDIM   1024
#define BATCH  16384

static constexpr int M_TILE = 128;
static constexpr int N_TILE = 128;
static constexpr int KT     = 64;            // K-chunk (elems)
static constexpr int NC2    = HDIM / KT;     // 16 chunks
static constexpr int NC     = HDIM / 32;     // 32 k32-granules (B frag layout)
static constexpr int SA     = 72;            // padded smem row stride (fp16)
static constexpr int STAGES = 3;

static constexpr int A_BYTES     = 128 * SA * 2;          // 18432
static constexpr int B_BYTES     = 16 * 2 * 512;          // 16 n8-tiles x 2 ksub x 512B
static constexpr int STG_BYTES   = A_BYTES + B_BYTES;     // 34816
static constexpr int OFF_B       = A_BYTES;
static constexpr int SMEM_BYTES  = STAGES * STG_BYTES;    // 104448

// --------------------------------------------------------------------------
__device__ __forceinline__ uint32_t smem_to_u32(const void* p) {
    uint32_t a;
    asm("{ .reg .u64 t; cvta.to.shared.u64 t, %1; cvt.u32.u64 %0, t; }" : "=r"(a) : "l"(p));
    return a;
}
#define CP_ASYNC16(s, g) \
    asm volatile("cp.async.cg.shared.global [%0], [%1], 16;" :: "r"(s), "l"(g) : "memory")
#define CP_COMMIT() asm volatile("cp.async.commit_group;" ::: "memory")
#define CP_WAIT1()  asm volatile("cp.async.wait_group 1;" ::: "memory")
#define CP_WAIT0()  asm volatile("cp.async.wait_group 0;" ::: "memory")
#define PREFETCH_L2(p) asm volatile("prefetch.global.L2 [%0];" :: "l"(p))

#define LDSM_X4(r0, r1, r2, r3, addr) \
    asm volatile("ldmatrix.sync.aligned.m8n8.x4.shared.b16 {%0,%1,%2,%3}, [%4];" \
                 : "=r"(r0), "=r"(r1), "=r"(r2), "=r"(r3) : "r"(addr))

#define LDS128(v, addr) \
    asm volatile("ld.shared.v4.u32 {%0,%1,%2,%3}, [%4];" \
                 : "=r"((v).x), "=r"((v).y), "=r"((v).z), "=r"((v).w) : "r"(addr))

#define MMA_F16_2(d, a, b0, b1) \
    asm volatile("mma.sync.aligned.m16n8k16.row.col.f32.f16.f16.f32 " \
                 "{%0,%1,%2,%3}, {%4,%5,%6,%7}, {%8,%9}, {%0,%1,%2,%3};" \
                 : "+f"((d)[0]), "+f"((d)[1]), "+f"((d)[2]), "+f"((d)[3]) \
                 : "r"((a)[0]), "r"((a)[1]), "r"((a)[2]), "r"((a)[3]), \
                   "r"(b0), "r"(b1))

// --------------------------------------------------------------------------
// Scratch (no cudaMalloc allowed)
// --------------------------------------------------------------------------
// B fragment-linear planes: index ((n8*NC + k32)*32 + lane) -> uint4 holding
// {b0,b1} for first k16 and {b0,b1} for second k16 of that k32 granule,
// per the m16n8k16 .col B layout (thread t: n=t/4, k=2*(t%4)+{0,1},+8,..).
__device__ uint4 g_W1f[(HDIM / 8) * NC * 32];
__device__ uint4 g_W2f[(HDIM / 8) * NC * 32];
__device__ __half g_Ph[(size_t)BATCH * HDIM];   // prev, fp16
__device__ __half g_Rh[(size_t)BATCH * HDIM];   // R = reset*state, fp16

__device__ __forceinline__ uint32_t pack_h2(__half a, __half b) {
    __half2 t; t.x = a; t.y = b;
    return *reinterpret_cast<uint32_t*>(&t);
}

// --------------------------------------------------------------------------
__global__ void wtrans_frag(const float* __restrict__ W, int ld, int off, int which) {
    const int t    = blockIdx.x * 256 + threadIdx.x;
    const int lane = t & 31;
    const int k32  = (t >> 5) & (NC - 1);
    const int n8   = t >> 10;
    const int n    = n8 * 8 + (lane >> 2);
    const int kb   = k32 * 32 + 2 * (lane & 3);
    uint32_t h[4];
#pragma unroll
    for (int w = 0; w < 4; w++) {
        const int k = kb + 8 * w;
        const float v0 = W[(size_t)k * ld + off + n];
        const float v1 = W[(size_t)(k + 1) * ld + off + n];
        h[w] = pack_h2(__float2half(v0), __float2half(v1));
    }
    uint4* F = which ? g_W2f : g_W1f;
    F[t] = make_uint4(h[0], h[1], h[2], h[3]);
}

// --------------------------------------------------------------------------
__global__ void psplit_kernel(const float* __restrict__ prev) {
    size_t i = ((size_t)blockIdx.x * 256 + threadIdx.x) * 4;
    float4 v = *reinterpret_cast<const float4*>(&prev[i]);
    uint32_t p01 = pack_h2(__float2half(v.x), __float2half(v.y));
    uint32_t p23 = pack_h2(__float2half(v.z), __float2half(v.w));
    *reinterpret_cast<uint2*>(&g_Ph[i]) = make_uint2(p01, p23);
}

// --------------------------------------------------------------------------
// GEMM: CTA 128x128, 8 warps (4M x 2N), warp tile 32x64, K-chunk 64,
// 3-stage cp.async pipeline, 16 iterations, epilogue-operand L2 prefetch.
// --------------------------------------------------------------------------
template <bool FIRST>
__global__ void __launch_bounds__(256, 2)
gemm_kernel(const float* __restrict__ inp, const float* __restrict__ prev,
            const float* __restrict__ mask, float* __restrict__ out) {
    extern __shared__ char smem_raw[];
    const uint32_t sb = smem_to_u32(smem_raw);

    const int tid   = threadIdx.x;
    const int wid   = tid >> 5;
    const int lane  = tid & 31;
    const int warpM = wid >> 1;       // 4 warps over M (32 rows each)
    const int warpN = wid & 1;        // 2 warps over N (64 cols each)
    const int m0 = blockIdx.x * M_TILE;
    const int n0 = blockIdx.y * N_TILE;

    const __half* AHg = FIRST ? g_Ph : g_Rh;
    const uint4* __restrict__ BF = FIRST ? g_W1f : g_W2f;
    const int nb0 = n0 >> 3;          // CTA's base n8 tile

    auto issue_chunk = [&](int kc, int stage) {
        const uint32_t s0 = sb + stage * STG_BYTES;
        // A: 128 rows x 8 granules (16B) = 1024 granules, 4/thread.
#pragma unroll
        for (int i = 0; i < 4; i++) {
            const int g   = tid + i * 256;
            const int row = g >> 3;
            const int ce  = (g & 7) * 8;
            const size_t gA = (size_t)(m0 + row) * HDIM + kc * KT + ce;
            const uint32_t so = (uint32_t)(row * SA + ce) * 2;
            CP_ASYNC16(s0 + so, AHg + gA);
        }
        // B: 16 tiles x 2 ksub x 32 lanes = 1024 granules, 4/thread.
#pragma unroll
        for (int i = 0; i < 4; i++) {
            const int g    = tid + i * 256;
            const int t8   = g >> 6;
            const int ksub = (g >> 5) & 1;
            const int ln   = g & 31;
            const int idx  = ((nb0 + t8) * NC + 2 * kc + ksub) * 32 + ln;
            CP_ASYNC16(s0 + OFF_B + (uint32_t)g * 16, &BF[idx]);
        }
    };

    float acc[2][8][4];
#pragma unroll
    for (int i = 0; i < 2; i++)
#pragma unroll
        for (int j = 0; j < 8; j++)
#pragma unroll
            for (int k = 0; k < 4; k++) acc[i][j][k] = 0.f;

    issue_chunk(0, 0); CP_COMMIT();
    issue_chunk(1, 1); CP_COMMIT();

    for (int c = 0; c < NC2; c++) {
        if (c == NC2 - 1) { CP_WAIT0(); } else { CP_WAIT1(); }
        __syncthreads();
        if (c + 2 < NC2) {
            issue_chunk(c + 2, (c + 2) % STAGES);
            CP_COMMIT();
        }

        // ---- L2 prefetch of this CTA's epilogue operands (one-shot, c==4).
        // si/gi planes: 128 rows x 512B = 512 lines each; prev16: 256 lines.
        if (c == 4) {
            if (FIRST) {
#pragma unroll
                for (int i = 0; i < 2; i++) {
                    const int l   = tid + i * 256;
                    const int row = l >> 2;
                    const int seg = (l & 3) * 128;
                    const char* ps = (const char*)&inp[(size_t)(m0 + row) * (3 * HDIM) + n0] + seg;
                    const char* pg = (const char*)&inp[(size_t)(m0 + row) * (3 * HDIM) + 2 * HDIM + n0] + seg;
                    PREFETCH_L2(ps);
                    PREFETCH_L2(pg);
                }
            } else {
#pragma unroll
                for (int i = 0; i < 2; i++) {
                    const int l   = tid + i * 256;
                    const int row = l >> 2;
                    const int seg = (l & 3) * 128;
                    const char* ps = (const char*)&inp[(size_t)(m0 + row) * (3 * HDIM) + n0] + seg;
                    PREFETCH_L2(ps);
                }
                {   // prev16 tile: 128 rows x 256B = 256 lines, 1/thread
                    const int row = tid >> 1;
                    const int seg = (tid & 1) * 128;
                    const char* pp = (const char*)&g_Ph[(size_t)(m0 + row) * HDIM + n0] + seg;
                    PREFETCH_L2(pp);
                }
            }
        }

        const uint32_t s0 = sb + (c % STAGES) * STG_BYTES;
        const uint32_t sBbase = s0 + OFF_B + (uint32_t)warpN * 8 * 1024 + lane * 16;

#pragma unroll
        for (int ksub = 0; ksub < 2; ksub++) {
            uint4 B4[8];
#pragma unroll
            for (int ni = 0; ni < 8; ni++)
                LDS128(B4[ni], sBbase + (uint32_t)(ni * 2 + ksub) * 512);

#pragma unroll
            for (int kb2 = 0; kb2 < 2; kb2++) {
                const int kcol = ksub * 32 + kb2 * 16 + ((lane >> 4) << 3);
                uint32_t a0[4], a1[4];
                {
                    const int r0 = warpM * 32 + (lane & 15);
                    const int r1 = warpM * 32 + 16 + (lane & 15);
                    const uint32_t o0 = (uint32_t)(r0 * SA + kcol) * 2;
                    const uint32_t o1 = (uint32_t)(r1 * SA + kcol) * 2;
                    LDSM_X4(a0[0], a0[1], a0[2], a0[3], s0 + o0);
                    LDSM_X4(a1[0], a1[1], a1[2], a1[3], s0 + o1);
                }
#pragma unroll
                for (int ni = 0; ni < 8; ni++) {
                    const uint32_t b0 = kb2 ? B4[ni].z : B4[ni].x;
                    const uint32_t b1 = kb2 ? B4[ni].w : B4[ni].y;
                    MMA_F16_2(acc[0][ni], a0, b0, b1);
                    MMA_F16_2(acc[1][ni], a1, b0, b1);
                }
            }
        }
    }

    // ---- epilogue ----
#pragma unroll
    for (int mi = 0; mi < 2; mi++) {
#pragma unroll
        for (int h = 0; h < 2; h++) {
            const int b = m0 + warpM * 32 + mi * 16 + h * 8 + (lane >> 2);
            float mval = 0.f;
            if (!FIRST) mval = __ldg(&mask[b]);
#pragma unroll
            for (int ni = 0; ni < 8; ni++) {
                const int n = n0 + warpN * 64 + ni * 8 + (lane & 3) * 2;
                const float v0 = acc[mi][ni][2 * h];
                const float v1 = acc[mi][ni][2 * h + 1];
                const float2 si = *reinterpret_cast<const float2*>(
                    &inp[(size_t)b * (3 * HDIM) + n]);
                if (FIRST) {
                    const float2 gi = *reinterpret_cast<const float2*>(
                        &inp[(size_t)b * (3 * HDIM) + 2 * HDIM + n]);
                    const float r0 = si.x / (1.f + __expf(-(v0 + gi.x)));
                    const float r1 = si.y / (1.f + __expf(-(v1 + gi.y)));
                    *reinterpret_cast<uint32_t*>(&g_Rh[(size_t)b * HDIM + n]) =
                        pack_h2(__float2half(r0), __float2half(r1));
                } else {
                    const __half2 ph = *reinterpret_cast<const __half2*>(
                        &g_Ph[(size_t)b * HDIM + n]);
                    const float2 pv = __half22float2(ph);
                    float2 o;
                    o.x = mval * (tanhf(v0 + si.x) + 1.f) + pv.x;
                    o.y = mval * (tanhf(v1 + si.y) + 1.f) + pv.y;
                    *reinterpret_cast<float2*>(&out[(size_t)b * HDIM + n]) = o;
                }
            }
        }
    }
}

// --------------------------------------------------------------------------
extern "C" void kernel_launch(void* const* d_in, const int* in_sizes, int n_in,
                              void* d_out, int out_size) {
    const float* inp  = (const float*)d_in[0];   // (B, 3H)
    const float* prev = (const float*)d_in[1];   // (B, H)
    const float* mask = (const float*)d_in[2];   // (B,)
    const float* Wur  = (const float*)d_in[3];   // (H, 2H)
    const float* U    = (const float*)d_in[4];   // (H, H)
    float* out = (float*)d_out;

    cudaFuncSetAttribute(gemm_kernel<true>,
                         cudaFuncAttributeMaxDynamicSharedMemorySize, SMEM_BYTES);
    cudaFuncSetAttribute(gemm_kernel<false>,
                         cudaFuncAttributeMaxDynamicSharedMemorySize, SMEM_BYTES);

    const int frag_slots = (HDIM / 8) * NC * 32;           // 131072
    wtrans_frag<<<frag_slots / 256, 256>>>(Wur, 2 * HDIM, HDIM, 0);  // Wr
    wtrans_frag<<<frag_slots / 256, 256>>>(U, HDIM, 0, 1);
    psplit_kernel<<<(BATCH * HDIM) / (256 * 4), 256>>>(prev);

    dim3 grid(BATCH / M_TILE, HDIM / N_TILE);
    gemm_kernel<true><<<grid, 256, SMEM_BYTES>>>(inp, prev, mask, out);
    gemm_kernel<false><<<grid, 256, SMEM_BYTES>>>(inp, prev, mask, out);
}

// round 14
// speedup vs baseline: 1.1445x; 1.0373x over previous
#include <cuda_runtime.h>
#include <cuda_fp16.h>
#include <cstdint>

// ============================================================================
// GGRUCell on GB300 — HMMA fp16 single-term GEMMs.
// R14 = R13 with the 2-stage pipeline RACE fixed: the refill of stage (c&1)
// is issued only AFTER the compute of chunk c has been barrier-drained.
// Epilogue operands stream into smem during chunks 16..31 (no cold-DRAM tail).
//
//   R   = sigmoid(prev @ Wr + inp[:,2H:]) * inp[:,:H]
//   out = mask * (tanh(R @ U + inp[:,:H]) + 1) + prev   (update gate cancels)
// ============================================================================

#define HDIM   1024
#define BATCH  16384

static constexpr int M_TILE = 128;
static constexpr int N_TILE = 128;
static constexpr int KT     = 32;            // K-chunk
static constexpr int NCH    = HDIM / KT;     // 32 chunks
static constexpr int NC     = HDIM / 32;     // 32 k32-granules (B frag layout)
static constexpr int SA     = 40;            // padded A smem row stride (fp16)
static constexpr int STAGES = 2;

static constexpr int A_BYTES    = 128 * SA * 2;           // 10240
static constexpr int B_BYTES    = 16 * 512;               // 16 n8-tiles x 512B
static constexpr int STG_BYTES  = A_BYTES + B_BYTES;      // 18432
static constexpr int OFF_B      = A_BYTES;
static constexpr int EPI_OFF    = STAGES * STG_BYTES;     // 36864
static constexpr int EPI_PITCH  = 272;                    // 256B data + 16B pad
static constexpr int EPI_PLANE  = 128 * EPI_PITCH;        // 34816
static constexpr int SMEM_BYTES = EPI_OFF + 2 * EPI_PLANE; // 106496

// --------------------------------------------------------------------------
__device__ __forceinline__ uint32_t smem_to_u32(const void* p) {
    uint32_t a;
    asm("{ .reg .u64 t; cvta.to.shared.u64 t, %1; cvt.u32.u64 %0, t; }" : "=r"(a) : "l"(p));
    return a;
}
#define CP_ASYNC16(s, g) \
    asm volatile("cp.async.cg.shared.global [%0], [%1], 16;" :: "r"(s), "l"(g) : "memory")
#define CP_COMMIT() asm volatile("cp.async.commit_group;" ::: "memory")
#define CP_WAIT1()  asm volatile("cp.async.wait_group 1;" ::: "memory")
#define CP_WAIT0()  asm volatile("cp.async.wait_group 0;" ::: "memory")

#define LDSM_X4(r0, r1, r2, r3, addr) \
    asm volatile("ldmatrix.sync.aligned.m8n8.x4.shared.b16 {%0,%1,%2,%3}, [%4];" \
                 : "=r"(r0), "=r"(r1), "=r"(r2), "=r"(r3) : "r"(addr))

#define LDS128(v, addr) \
    asm volatile("ld.shared.v4.u32 {%0,%1,%2,%3}, [%4];" \
                 : "=r"((v).x), "=r"((v).y), "=r"((v).z), "=r"((v).w) : "r"(addr))

#define LDSH2F(f2, addr) do { \
    uint32_t _u; \
    asm volatile("ld.shared.b32 %0, [%1];" : "=r"(_u) : "r"(addr)); \
    __half2 _h = *reinterpret_cast<__half2*>(&_u); \
    (f2) = __half22float2(_h); \
} while (0)

#define MMA_F16_2(d, a, b0, b1) \
    asm volatile("mma.sync.aligned.m16n8k16.row.col.f32.f16.f16.f32 " \
                 "{%0,%1,%2,%3}, {%4,%5,%6,%7}, {%8,%9}, {%0,%1,%2,%3};" \
                 : "+f"((d)[0]), "+f"((d)[1]), "+f"((d)[2]), "+f"((d)[3]) \
                 : "r"((a)[0]), "r"((a)[1]), "r"((a)[2]), "r"((a)[3]), \
                   "r"(b0), "r"(b1))

// --------------------------------------------------------------------------
// Scratch (no cudaMalloc allowed)
// --------------------------------------------------------------------------
__device__ uint4 g_W1f[(HDIM / 8) * NC * 32];   // Wr fragment-linear fp16
__device__ uint4 g_W2f[(HDIM / 8) * NC * 32];   // U  fragment-linear fp16
__device__ __half g_Ph[(size_t)BATCH * HDIM];   // prev  fp16
__device__ __half g_S16[(size_t)BATCH * HDIM];  // state_inp (si) fp16
__device__ __half g_G16[(size_t)BATCH * HDIM];  // gate_inp (reset half) fp16
__device__ __half g_Rh[(size_t)BATCH * HDIM];   // R = reset*state fp16

__device__ __forceinline__ uint32_t pack_h2(__half a, __half b) {
    __half2 t; t.x = a; t.y = b;
    return *reinterpret_cast<uint32_t*>(&t);
}
__device__ __forceinline__ uint2 cvt2h4(float4 v) {
    return make_uint2(pack_h2(__float2half(v.x), __float2half(v.y)),
                      pack_h2(__float2half(v.z), __float2half(v.w)));
}

// --------------------------------------------------------------------------
// Fused prep: inp[:, :H] -> si16, inp[:, 2H:] -> gi16, prev -> prev16.
// --------------------------------------------------------------------------
__global__ void prep_kernel(const float* __restrict__ inp,
                            const float* __restrict__ prev) {
    const size_t i = ((size_t)blockIdx.x * 256 + threadIdx.x) * 4;
    const int row = (int)(i >> 10);
    const int col = (int)(i & 1023);
    const float4 sv = *reinterpret_cast<const float4*>(&inp[(size_t)row * 3072 + col]);
    const float4 gv = *reinterpret_cast<const float4*>(&inp[(size_t)row * 3072 + 2048 + col]);
    const float4 pv = *reinterpret_cast<const float4*>(&prev[i]);
    *reinterpret_cast<uint2*>(&g_S16[i]) = cvt2h4(sv);
    *reinterpret_cast<uint2*>(&g_G16[i]) = cvt2h4(gv);
    *reinterpret_cast<uint2*>(&g_Ph[i])  = cvt2h4(pv);
}

// --------------------------------------------------------------------------
// Weight -> fragment-linear fp16 plane (m16n8k16 .col B layout).
// --------------------------------------------------------------------------
__global__ void wtrans_frag(const float* __restrict__ W, int ld, int off, int which) {
    const int t    = blockIdx.x * 256 + threadIdx.x;
    const int lane = t & 31;
    const int k32  = (t >> 5) & (NC - 1);
    const int n8   = t >> 10;
    const int n    = n8 * 8 + (lane >> 2);
    const int kb   = k32 * 32 + 2 * (lane & 3);
    uint32_t h[4];
#pragma unroll
    for (int w = 0; w < 4; w++) {
        const int k = kb + 8 * w;
        const float v0 = W[(size_t)k * ld + off + n];
        const float v1 = W[(size_t)(k + 1) * ld + off + n];
        h[w] = pack_h2(__float2half(v0), __float2half(v1));
    }
    uint4* F = which ? g_W2f : g_W1f;
    F[t] = make_uint4(h[0], h[1], h[2], h[3]);
}

// --------------------------------------------------------------------------
// GEMM: CTA 128x128, 8 warps (4M x 2N), warp tile 32x64, K-chunk 32,
// 2-stage cp.async (refill AFTER compute drain); epi tiles streamed in
// during chunks 16..31.
// --------------------------------------------------------------------------
template <bool FIRST>
__global__ void __launch_bounds__(256, 2)
gemm_kernel(const float* __restrict__ mask, float* __restrict__ out) {
    extern __shared__ char smem_raw[];
    const uint32_t sb = smem_to_u32(smem_raw);

    const int tid   = threadIdx.x;
    const int wid   = tid >> 5;
    const int lane  = tid & 31;
    const int warpM = wid >> 1;       // 4 warps over M (32 rows each)
    const int warpN = wid & 1;        // 2 warps over N (64 cols each)
    const int m0 = blockIdx.x * M_TILE;
    const int n0 = blockIdx.y * N_TILE;

    const __half* AHg = FIRST ? g_Ph : g_Rh;
    const uint4* __restrict__ BF = FIRST ? g_W1f : g_W2f;
    const int nb0 = n0 >> 3;

    auto issue_chunk = [&](int kc, int stage) {
        const uint32_t s0 = sb + stage * STG_BYTES;
#pragma unroll
        for (int i = 0; i < 2; i++) {
            const int g   = tid + i * 256;
            const int row = g >> 2;
            const int ce  = (g & 3) * 8;
            const size_t gA = (size_t)(m0 + row) * HDIM + kc * KT + ce;
            const uint32_t so = (uint32_t)(row * SA + ce) * 2;
            CP_ASYNC16(s0 + so, AHg + gA);
        }
#pragma unroll
        for (int i = 0; i < 2; i++) {
            const int g  = tid + i * 256;
            const int t8 = g >> 5;
            const int ln = g & 31;
            const int idx = ((nb0 + t8) * NC + kc) * 32 + ln;
            CP_ASYNC16(s0 + OFF_B + (uint32_t)g * 16, &BF[idx]);
        }
    };

    // epi slice s (0..15): 8 rows x 16 granules x 2 planes = 256 granules
    auto issue_epi = [&](int s) {
        const int plane = tid >> 7;                 // 0: si16, 1: gi16/prev16
        const int rl    = 8 * s + ((tid & 127) >> 4);
        const int g     = tid & 15;
        const __half* src = plane ? (FIRST ? g_G16 : g_Ph) : g_S16;
        const size_t ga = (size_t)(m0 + rl) * HDIM + n0 + g * 8;
        const uint32_t da = sb + EPI_OFF + plane * EPI_PLANE + rl * EPI_PITCH + g * 16;
        CP_ASYNC16(da, src + ga);
    };

    float acc[2][8][4];
#pragma unroll
    for (int i = 0; i < 2; i++)
#pragma unroll
        for (int j = 0; j < 8; j++)
#pragma unroll
            for (int k = 0; k < 4; k++) acc[i][j][k] = 0.f;

    issue_chunk(0, 0); CP_COMMIT();
    issue_chunk(1, 1); CP_COMMIT();

    for (int c = 0; c < NCH; c++) {
        CP_WAIT1();                 // chunk c's group complete
        __syncthreads();            // its smem writes visible to all warps

        const uint32_t s0 = sb + (c & 1) * STG_BYTES;
        const uint32_t sB = s0 + OFF_B + (uint32_t)warpN * 8 * 512 + lane * 16;

        uint4 B4[8];
#pragma unroll
        for (int ni = 0; ni < 8; ni++) LDS128(B4[ni], sB + ni * 512);

#pragma unroll
        for (int kb2 = 0; kb2 < 2; kb2++) {
            const int kcol = kb2 * 16 + ((lane >> 4) << 3);
            uint32_t a0[4], a1[4];
            {
                const int r0 = warpM * 32 + (lane & 15);
                const int r1 = warpM * 32 + 16 + (lane & 15);
                const uint32_t o0 = (uint32_t)(r0 * SA + kcol) * 2;
                const uint32_t o1 = (uint32_t)(r1 * SA + kcol) * 2;
                LDSM_X4(a0[0], a0[1], a0[2], a0[3], s0 + o0);
                LDSM_X4(a1[0], a1[1], a1[2], a1[3], s0 + o1);
            }
#pragma unroll
            for (int ni = 0; ni < 8; ni++) {
                const uint32_t b0 = kb2 ? B4[ni].z : B4[ni].x;
                const uint32_t b1 = kb2 ? B4[ni].w : B4[ni].y;
                MMA_F16_2(acc[0][ni], a0, b0, b1);
                MMA_F16_2(acc[1][ni], a1, b0, b1);
            }
        }
        __syncthreads();            // ALL warps done reading stage c&1

        // refill now — stage c&1 is free; one commit group per iteration
        if (c + 2 < NCH) issue_chunk(c + 2, (c + 2) & 1);
        if (c >= 16)     issue_epi(c - 16);
        CP_COMMIT();
    }

    CP_WAIT0();                     // all epi slices landed
    __syncthreads();

    // ---- epilogue (operands in smem) ----
    const uint32_t e0 = sb + EPI_OFF;              // si16
    const uint32_t e1 = e0 + EPI_PLANE;            // gi16 (G1) / prev16 (G2)
#pragma unroll
    for (int mi = 0; mi < 2; mi++) {
#pragma unroll
        for (int h = 0; h < 2; h++) {
            const int row = warpM * 32 + mi * 16 + h * 8 + (lane >> 2);
            const int b   = m0 + row;
            float mval = 0.f;
            if (!FIRST) mval = __ldg(&mask[b]);
#pragma unroll
            for (int ni = 0; ni < 8; ni++) {
                const int col = warpN * 64 + ni * 8 + (lane & 3) * 2;
                const uint32_t so = (uint32_t)(row * EPI_PITCH + col * 2);
                const float v0 = acc[mi][ni][2 * h];
                const float v1 = acc[mi][ni][2 * h + 1];
                float2 sif; LDSH2F(sif, e0 + so);
                if (FIRST) {
                    float2 gif; LDSH2F(gif, e1 + so);
                    const float r0 = sif.x / (1.f + __expf(-(v0 + gif.x)));
                    const float r1 = sif.y / (1.f + __expf(-(v1 + gif.y)));
                    *reinterpret_cast<uint32_t*>(&g_Rh[(size_t)b * HDIM + n0 + col]) =
                        pack_h2(__float2half(r0), __float2half(r1));
                } else {
                    float2 pvf; LDSH2F(pvf, e1 + so);
                    float2 o;
                    o.x = mval * (tanhf(v0 + sif.x) + 1.f) + pvf.x;
                    o.y = mval * (tanhf(v1 + sif.y) + 1.f) + pvf.y;
                    *reinterpret_cast<float2*>(&out[(size_t)b * HDIM + n0 + col]) = o;
                }
            }
        }
    }
}

// --------------------------------------------------------------------------
extern "C" void kernel_launch(void* const* d_in, const int* in_sizes, int n_in,
                              void* d_out, int out_size) {
    const float* inp  = (const float*)d_in[0];   // (B, 3H)
    const float* prev = (const float*)d_in[1];   // (B, H)
    const float* mask = (const float*)d_in[2];   // (B,)
    const float* Wur  = (const float*)d_in[3];   // (H, 2H)
    const float* U    = (const float*)d_in[4];   // (H, H)
    float* out = (float*)d_out;

    cudaFuncSetAttribute(gemm_kernel<true>,
                         cudaFuncAttributeMaxDynamicSharedMemorySize, SMEM_BYTES);
    cudaFuncSetAttribute(gemm_kernel<false>,
                         cudaFuncAttributeMaxDynamicSharedMemorySize, SMEM_BYTES);

    prep_kernel<<<(BATCH * HDIM) / (256 * 4), 256>>>(inp, prev);
    const int frag_slots = (HDIM / 8) * NC * 32;           // 131072
    wtrans_frag<<<frag_slots / 256, 256>>>(Wur, 2 * HDIM, HDIM, 0);  // Wr
    wtrans_frag<<<frag_slots / 256, 256>>>(U, HDIM, 0, 1);

    dim3 grid(BATCH / M_TILE, HDIM / N_TILE);
    gemm_kernel<true><<<grid, 256, SMEM_BYTES>>>(mask, out);
    gemm_kernel<false><<<grid, 256, SMEM_BYTES>>>(mask, out);
}

// round 15
// speedup vs baseline: 1.1584x; 1.0122x over previous
#include <cuda_runtime.h>
#include <cuda_fp16.h>
#include <cstdint>

// ============================================================================
// GGRUCell on GB300 — HMMA fp16 single-term GEMMs.
// R15 = R14 + in-GEMM epilogue-operand conversion: raw fp32 si/gi slices are
// cp.async-staged and converted to fp16 epi planes DURING the mainloop,
// killing 2/3 of the prep kernel (only prev->fp16 remains).
// Group-c invariant: chunk c, staging slice c all live in commit-group c,
// complete at top of iteration c under cp.async.wait_group 1.
//
//   R   = sigmoid(prev @ Wr + inp[:,2H:]) * inp[:,:H]
//   out = mask * (tanh(R @ U + inp[:,:H]) + 1) + prev   (update gate cancels)
// ============================================================================

#define HDIM   1024
#define BATCH  16384

static constexpr int M_TILE = 128;
static constexpr int N_TILE = 128;
static constexpr int KT     = 32;            // K-chunk
static constexpr int NCH    = HDIM / KT;     // 32 chunks
static constexpr int NC     = HDIM / 32;     // 32 k32-granules (B frag layout)
static constexpr int SA     = 40;            // padded A smem row stride (fp16)

static constexpr int A_BYTES    = 128 * SA * 2;           // 10240
static constexpr int B_BYTES    = 16 * 512;               // 8192
static constexpr int STG_BYTES  = A_BYTES + B_BYTES;      // 18432
static constexpr int OFF_B      = A_BYTES;
static constexpr int EPI_OFF    = 2 * STG_BYTES;          // 36864
static constexpr int PITCH_S    = 264;  // converted planes (STS, 8B align ok)
static constexpr int PITCH_P    = 272;  // prev16 plane (cp.async, 16B align)
static constexpr int PLANE_S    = 128 * PITCH_S;          // 33792
static constexpr int PLANE_P    = 128 * PITCH_P;          // 34816
// FIRST : e0=si16(PL_S) e1=gi16(PL_S) staging 2x4096
// !FIRST: e0=si16(PL_S) e1=prev16(PL_P) staging 2x2048
static constexpr int SMEM_BYTES = EPI_OFF + 2 * PLANE_S + 2 * 4096;  // 112640

// --------------------------------------------------------------------------
__device__ __forceinline__ uint32_t smem_to_u32(const void* p) {
    uint32_t a;
    asm("{ .reg .u64 t; cvta.to.shared.u64 t, %1; cvt.u32.u64 %0, t; }" : "=r"(a) : "l"(p));
    return a;
}
#define CP_ASYNC16(s, g) \
    asm volatile("cp.async.cg.shared.global [%0], [%1], 16;" :: "r"(s), "l"(g) : "memory")
#define CP_COMMIT() asm volatile("cp.async.commit_group;" ::: "memory")
#define CP_WAIT1()  asm volatile("cp.async.wait_group 1;" ::: "memory")
#define CP_WAIT0()  asm volatile("cp.async.wait_group 0;" ::: "memory")

#define LDSM_X4(r0, r1, r2, r3, addr) \
    asm volatile("ldmatrix.sync.aligned.m8n8.x4.shared.b16 {%0,%1,%2,%3}, [%4];" \
                 : "=r"(r0), "=r"(r1), "=r"(r2), "=r"(r3) : "r"(addr))

#define LDS128(v, addr) \
    asm volatile("ld.shared.v4.u32 {%0,%1,%2,%3}, [%4];" \
                 : "=r"((v).x), "=r"((v).y), "=r"((v).z), "=r"((v).w) : "r"(addr))

#define LDSF4(v, addr) \
    asm volatile("ld.shared.v4.f32 {%0,%1,%2,%3}, [%4];" \
                 : "=f"((v).x), "=f"((v).y), "=f"((v).z), "=f"((v).w) : "r"(addr))

#define STS8(addr, a, b) \
    asm volatile("st.shared.v2.b32 [%0], {%1, %2};" :: "r"(addr), "r"(a), "r"(b) : "memory")

#define LDSH2F(f2, addr) do { \
    uint32_t _u; \
    asm volatile("ld.shared.b32 %0, [%1];" : "=r"(_u) : "r"(addr)); \
    __half2 _h = *reinterpret_cast<__half2*>(&_u); \
    (f2) = __half22float2(_h); \
} while (0)

#define MMA_F16_2(d, a, b0, b1) \
    asm volatile("mma.sync.aligned.m16n8k16.row.col.f32.f16.f16.f32 " \
                 "{%0,%1,%2,%3}, {%4,%5,%6,%7}, {%8,%9}, {%0,%1,%2,%3};" \
                 : "+f"((d)[0]), "+f"((d)[1]), "+f"((d)[2]), "+f"((d)[3]) \
                 : "r"((a)[0]), "r"((a)[1]), "r"((a)[2]), "r"((a)[3]), \
                   "r"(b0), "r"(b1))

// --------------------------------------------------------------------------
// Scratch (no cudaMalloc allowed)
// --------------------------------------------------------------------------
__device__ uint4 g_W1f[(HDIM / 8) * NC * 32];   // Wr fragment-linear fp16
__device__ uint4 g_W2f[(HDIM / 8) * NC * 32];   // U  fragment-linear fp16
__device__ __half g_Ph[(size_t)BATCH * HDIM];   // prev  fp16
__device__ __half g_Rh[(size_t)BATCH * HDIM];   // R = reset*state fp16

__device__ __forceinline__ uint32_t pack_h2(__half a, __half b) {
    __half2 t; t.x = a; t.y = b;
    return *reinterpret_cast<uint32_t*>(&t);
}

// --------------------------------------------------------------------------
// prep: prev -> fp16 only.
// --------------------------------------------------------------------------
__global__ void prep_kernel(const float* __restrict__ prev) {
    const size_t i = ((size_t)blockIdx.x * 256 + threadIdx.x) * 4;
    const float4 pv = *reinterpret_cast<const float4*>(&prev[i]);
    *reinterpret_cast<uint2*>(&g_Ph[i]) = make_uint2(
        pack_h2(__float2half(pv.x), __float2half(pv.y)),
        pack_h2(__float2half(pv.z), __float2half(pv.w)));
}

// --------------------------------------------------------------------------
// Weight -> fragment-linear fp16 plane (m16n8k16 .col B layout).
// --------------------------------------------------------------------------
__global__ void wtrans_frag(const float* __restrict__ W, int ld, int off, int which) {
    const int t    = blockIdx.x * 256 + threadIdx.x;
    const int lane = t & 31;
    const int k32  = (t >> 5) & (NC - 1);
    const int n8   = t >> 10;
    const int n    = n8 * 8 + (lane >> 2);
    const int kb   = k32 * 32 + 2 * (lane & 3);
    uint32_t h[4];
#pragma unroll
    for (int w = 0; w < 4; w++) {
        const int k = kb + 8 * w;
        const float v0 = W[(size_t)k * ld + off + n];
        const float v1 = W[(size_t)(k + 1) * ld + off + n];
        h[w] = pack_h2(__float2half(v0), __float2half(v1));
    }
    uint4* F = which ? g_W2f : g_W1f;
    F[t] = make_uint4(h[0], h[1], h[2], h[3]);
}

// --------------------------------------------------------------------------
// GEMM: CTA 128x128, 8 warps (4M x 2N), warp tile 32x64, K-chunk 32.
// Epi operands: fp32 slices (4 rows) staged + converted in-loop.
// --------------------------------------------------------------------------
template <bool FIRST>
__global__ void __launch_bounds__(256, 2)
gemm_kernel(const float* __restrict__ inp, const float* __restrict__ mask,
            float* __restrict__ out) {
    extern __shared__ char smem_raw[];
    const uint32_t sb = smem_to_u32(smem_raw);

    const int tid   = threadIdx.x;
    const int wid   = tid >> 5;
    const int lane  = tid & 31;
    const int warpM = wid >> 1;       // 4 warps over M (32 rows each)
    const int warpN = wid & 1;        // 2 warps over N (64 cols each)
    const int m0 = blockIdx.x * M_TILE;
    const int n0 = blockIdx.y * N_TILE;

    const __half* AHg = FIRST ? g_Ph : g_Rh;
    const uint4* __restrict__ BF = FIRST ? g_W1f : g_W2f;
    const int nb0 = n0 >> 3;

    const uint32_t e0   = sb + EPI_OFF;                          // si16
    const uint32_t e1   = e0 + PLANE_S;                          // gi16 / prev16
    const uint32_t stg  = FIRST ? (e1 + PLANE_S) : (e1 + PLANE_P);
    const uint32_t SSZ  = FIRST ? 4096u : 2048u;                 // staging buf size

    auto issue_chunk = [&](int kc, int stage) {
        const uint32_t s0 = sb + stage * STG_BYTES;
#pragma unroll
        for (int i = 0; i < 2; i++) {
            const int g   = tid + i * 256;
            const int row = g >> 2;
            const int ce  = (g & 3) * 8;
            const size_t gA = (size_t)(m0 + row) * HDIM + kc * KT + ce;
            const uint32_t so = (uint32_t)(row * SA + ce) * 2;
            CP_ASYNC16(s0 + so, AHg + gA);
        }
#pragma unroll
        for (int i = 0; i < 2; i++) {
            const int g  = tid + i * 256;
            const int t8 = g >> 5;
            const int ln = g & 31;
            const int idx = ((nb0 + t8) * NC + kc) * 32 + ln;
            CP_ASYNC16(s0 + OFF_B + (uint32_t)g * 16, &BF[idx]);
        }
    };

    // slice s (0..31): rows 4s..4s+3.
    auto issue_slice = [&](int s) {
        if (FIRST) {
            // 2 fp32 planes (si, gi): 256 granules, 1/thread
            const int p  = tid >> 7;
            const int r  = (tid >> 5) & 3;
            const int c4 = tid & 31;
            const float* src = inp + (size_t)(m0 + 4 * s + r) * 3072
                               + (p ? 2048 : 0) + n0 + c4 * 4;
            const uint32_t dst = stg + (s & 1) * SSZ + p * 2048 + r * 512 + c4 * 16;
            CP_ASYNC16(dst, src);
        } else {
            if (tid < 128) {      // si fp32: 128 granules
                const int r  = (tid >> 5) & 3;
                const int c4 = tid & 31;
                const float* src = inp + (size_t)(m0 + 4 * s + r) * 3072 + n0 + c4 * 4;
                const uint32_t dst = stg + (s & 1) * SSZ + r * 512 + c4 * 16;
                CP_ASYNC16(dst, src);
            } else if (tid < 192) {  // prev16 direct: 64 granules into e1
                const int h  = tid - 128;
                const int r  = h >> 4;
                const int c8 = h & 15;
                const __half* src = g_Ph + (size_t)(m0 + 4 * s + r) * HDIM + n0 + c8 * 8;
                const uint32_t dst = e1 + (uint32_t)(4 * s + r) * PITCH_P + c8 * 16;
                CP_ASYNC16(dst, src);
            }
        }
    };

    auto convert_slice = [&](int s) {
        if (FIRST) {
            const int p  = tid >> 7;
            const int r  = (tid >> 5) & 3;
            const int c4 = tid & 31;
            float4 v;
            LDSF4(v, stg + (s & 1) * SSZ + p * 2048 + r * 512 + c4 * 16);
            const uint32_t d = (p ? e1 : e0) + (uint32_t)(4 * s + r) * PITCH_S + c4 * 8;
            STS8(d, pack_h2(__float2half(v.x), __float2half(v.y)),
                    pack_h2(__float2half(v.z), __float2half(v.w)));
        } else {
            if (tid < 128) {
                const int r  = (tid >> 5) & 3;
                const int c4 = tid & 31;
                float4 v;
                LDSF4(v, stg + (s & 1) * SSZ + r * 512 + c4 * 16);
                const uint32_t d = e0 + (uint32_t)(4 * s + r) * PITCH_S + c4 * 8;
                STS8(d, pack_h2(__float2half(v.x), __float2half(v.y)),
                        pack_h2(__float2half(v.z), __float2half(v.w)));
            }
        }
    };

    float acc[2][8][4];
#pragma unroll
    for (int i = 0; i < 2; i++)
#pragma unroll
        for (int j = 0; j < 8; j++)
#pragma unroll
            for (int k = 0; k < 4; k++) acc[i][j][k] = 0.f;

    // group 0: chunk 0 + slice 0 ; group 1: chunk 1 + slice 1
    issue_chunk(0, 0); issue_slice(0); CP_COMMIT();
    issue_chunk(1, 1); issue_slice(1); CP_COMMIT();

    for (int c = 0; c < NCH; c++) {
        CP_WAIT1();                 // group c complete
        __syncthreads();

        const uint32_t s0 = sb + (c & 1) * STG_BYTES;
        const uint32_t sB = s0 + OFF_B + (uint32_t)warpN * 8 * 512 + lane * 16;

        uint4 B4[8];
#pragma unroll
        for (int ni = 0; ni < 8; ni++) LDS128(B4[ni], sB + ni * 512);

        convert_slice(c);           // slice c staged in group c -> epi planes

#pragma unroll
        for (int kb2 = 0; kb2 < 2; kb2++) {
            const int kcol = kb2 * 16 + ((lane >> 4) << 3);
            uint32_t a0[4], a1[4];
            {
                const int r0 = warpM * 32 + (lane & 15);
                const int r1 = warpM * 32 + 16 + (lane & 15);
                const uint32_t o0 = (uint32_t)(r0 * SA + kcol) * 2;
                const uint32_t o1 = (uint32_t)(r1 * SA + kcol) * 2;
                LDSM_X4(a0[0], a0[1], a0[2], a0[3], s0 + o0);
                LDSM_X4(a1[0], a1[1], a1[2], a1[3], s0 + o1);
            }
#pragma unroll
            for (int ni = 0; ni < 8; ni++) {
                const uint32_t b0 = kb2 ? B4[ni].z : B4[ni].x;
                const uint32_t b1 = kb2 ? B4[ni].w : B4[ni].y;
                MMA_F16_2(acc[0][ni], a0, b0, b1);
                MMA_F16_2(acc[1][ni], a1, b0, b1);
            }
        }
        __syncthreads();            // stage c&1 + staging buf c&1 drained

        if (c + 2 < NCH) {          // group c+2: chunk c+2 + slice c+2
            issue_chunk(c + 2, (c + 2) & 1);
            issue_slice(c + 2);
        }
        CP_COMMIT();
    }

    CP_WAIT0();
    __syncthreads();                // epi-plane STS + prev16 cp.async visible

    // ---- epilogue (operands in smem) ----
#pragma unroll
    for (int mi = 0; mi < 2; mi++) {
#pragma unroll
        for (int h = 0; h < 2; h++) {
            const int row = warpM * 32 + mi * 16 + h * 8 + (lane >> 2);
            const int b   = m0 + row;
            float mval = 0.f;
            if (!FIRST) mval = __ldg(&mask[b]);
#pragma unroll
            for (int ni = 0; ni < 8; ni++) {
                const int col = warpN * 64 + ni * 8 + (lane & 3) * 2;
                const float v0 = acc[mi][ni][2 * h];
                const float v1 = acc[mi][ni][2 * h + 1];
                float2 sif; LDSH2F(sif, e0 + (uint32_t)(row * PITCH_S + col * 2));
                if (FIRST) {
                    float2 gif; LDSH2F(gif, e1 + (uint32_t)(row * PITCH_S + col * 2));
                    const float r0 = sif.x / (1.f + __expf(-(v0 + gif.x)));
                    const float r1 = sif.y / (1.f + __expf(-(v1 + gif.y)));
                    *reinterpret_cast<uint32_t*>(&g_Rh[(size_t)b * HDIM + n0 + col]) =
                        pack_h2(__float2half(r0), __float2half(r1));
                } else {
                    float2 pvf; LDSH2F(pvf, e1 + (uint32_t)(row * PITCH_P + col * 2));
                    float2 o;
                    o.x = mval * (tanhf(v0 + sif.x) + 1.f) + pvf.x;
                    o.y = mval * (tanhf(v1 + sif.y) + 1.f) + pvf.y;
                    *reinterpret_cast<float2*>(&out[(size_t)b * HDIM + n0 + col]) = o;
                }
            }
        }
    }
}

// --------------------------------------------------------------------------
extern "C" void kernel_launch(void* const* d_in, const int* in_sizes, int n_in,
                              void* d_out, int out_size) {
    const float* inp  = (const float*)d_in[0];   // (B, 3H)
    const float* prev = (const float*)d_in[1];   // (B, H)
    const float* mask = (const float*)d_in[2];   // (B,)
    const float* Wur  = (const float*)d_in[3];   // (H, 2H)
    const float* U    = (const float*)d_in[4];   // (H, H)
    float* out = (float*)d_out;

    cudaFuncSetAttribute(gemm_kernel<true>,
                         cudaFuncAttributeMaxDynamicSharedMemorySize, SMEM_BYTES);
    cudaFuncSetAttribute(gemm_kernel<false>,
                         cudaFuncAttributeMaxDynamicSharedMemorySize, SMEM_BYTES);

    prep_kernel<<<(BATCH * HDIM) / (256 * 4), 256>>>(prev);
    const int frag_slots = (HDIM / 8) * NC * 32;           // 131072
    wtrans_frag<<<frag_slots / 256, 256>>>(Wur, 2 * HDIM, HDIM, 0);  // Wr
    wtrans_frag<<<frag_slots / 256, 256>>>(U, HDIM, 0, 1);

    dim3 grid(BATCH / M_TILE, HDIM / N_TILE);
    gemm_kernel<true><<<grid, 256, SMEM_BYTES>>>(inp, mask, out);
    gemm_kernel<false><<<grid, 256, SMEM_BYTES>>>(inp, mask, out);
}